// round 2
// baseline (speedup 1.0000x reference)
#include <cuda_runtime.h>
#include <cstdint>

#define BB 32
#define TT 36
#define NN 10000
#define FF 3
#define HH 10
#define RR 20

#define NTILE   2560
#define NBLKX   4            // ceil(NN / NTILE)
#define THREADS 512
#define KPT     5            // NTILE / THREADS
#define STAGES  4
#define STAGE_BYTES (NTILE * FF * 4)   // 30720 B
#define SMEM_BYTES  (STAGES * STAGE_BYTES)

// ---- device scratch (no allocations allowed) ----
__device__ float g_rsum[BB * RR];
__device__ float g_rcnt[BB * RR];
__device__ float g_g1;
__device__ int   g_is64;
__device__ int   g_nan_count;
__device__ int   g_nan_list[BB * NN];

// ---------------- PTX helpers ----------------
__device__ __forceinline__ void mbar_init(uint32_t addr, uint32_t count) {
    asm volatile("mbarrier.init.shared.b64 [%0], %1;" :: "r"(addr), "r"(count));
}
__device__ __forceinline__ void mbar_expect_tx(uint32_t addr, uint32_t bytes) {
    asm volatile("mbarrier.arrive.expect_tx.shared.b64 _, [%0], %1;"
                 :: "r"(addr), "r"(bytes) : "memory");
}
__device__ __forceinline__ void bulk_g2s(uint32_t smem_dst, const void* gmem_src,
                                         uint32_t bytes, uint32_t mbar) {
    asm volatile("cp.async.bulk.shared::cta.global.mbarrier::complete_tx::bytes "
                 "[%0], [%1], %2, [%3];"
                 :: "r"(smem_dst), "l"(gmem_src), "r"(bytes), "r"(mbar) : "memory");
}
__device__ __forceinline__ void mbar_wait(uint32_t addr, uint32_t phase) {
    asm volatile("{\n\t.reg .pred p;\n"
                 "WAIT_%=:\n\t"
                 "mbarrier.try_wait.parity.acquire.cta.shared::cta.b64 p, [%0], %1, 0x989680;\n\t"
                 "@!p bra WAIT_%=;\n\t}"
                 :: "r"(addr), "r"(phase) : "memory");
}

// ---------------------------------------------------------------------------
// Kernel 0: zero accumulators + detect cluster_id dtype (int32 vs int64-LE).
// ---------------------------------------------------------------------------
__global__ void k_init(const int* __restrict__ cid32) {
    int tid = threadIdx.x;
    for (int i = tid; i < BB * RR; i += blockDim.x) {
        g_rsum[i] = 0.0f;
        g_rcnt[i] = 0.0f;
    }
    if (tid == 0) g_nan_count = 0;
    int zc = 0;
    for (int i = tid; i < NN / 2; i += blockDim.x)
        if (cid32[2 * i + 1] == 0) zc++;
    __shared__ int s_z;
    if (tid == 0) s_z = 0;
    __syncthreads();
    atomicAdd(&s_z, zc);
    __syncthreads();
    if (tid == 0) g_is64 = (s_z > 4000) ? 1 : 0;
}

// ---------------------------------------------------------------------------
// Kernel 1 (fused): bulk-copy pipelined temporal nanmean + out_pred writes +
// region partials. grid = (NBLKX, BB), block = 512, dynamic smem 120KB.
// ---------------------------------------------------------------------------
extern __shared__ float4 smem_raw[];

__global__ void __launch_bounds__(THREADS, 1)
k_mean(const float* __restrict__ seq, const int* __restrict__ cid32,
       float* __restrict__ out) {
    __shared__ __align__(8) unsigned long long mbar[STAGES];
    __shared__ float srs[RR], src[RR];

    float* sm = reinterpret_cast<float*>(smem_raw);
    const int tid = threadIdx.x;
    const int b   = blockIdx.y;
    const int n0  = blockIdx.x * NTILE;
    const int nvalid = min(NTILE, NN - n0);
    const uint32_t bytes = (uint32_t)nvalid * FF * 4u;   // multiple of 16

    const uint32_t mb0 = (uint32_t)__cvta_generic_to_shared(&mbar[0]);
    const uint32_t sm0 = (uint32_t)__cvta_generic_to_shared(sm);

    if (tid < RR) { srs[tid] = 0.0f; src[tid] = 0.0f; }
    if (tid == 0) {
#pragma unroll
        for (int s = 0; s < STAGES; s++) mbar_init(mb0 + s * 8, 1);
    }
    __syncthreads();

    // global base for this (b, tile): ((b*T + t)*N + n0)*F
    const float* gbase = seq + (size_t)b * TT * NN * FF + (size_t)n0 * FF;

    if (tid == 0) {
#pragma unroll
        for (int s = 0; s < STAGES; s++) {
            mbar_expect_tx(mb0 + s * 8, bytes);
            bulk_g2s(sm0 + s * STAGE_BYTES, gbase + (size_t)s * NN * FF, bytes, mb0 + s * 8);
        }
    }

    float acc_s[KPT], acc_c[KPT];
#pragma unroll
    for (int k = 0; k < KPT; k++) { acc_s[k] = 0.0f; acc_c[k] = 0.0f; }

    for (int t = 0; t < TT; t++) {
        const int st = t & (STAGES - 1);
        mbar_wait(mb0 + st * 8, (t >> 2) & 1);
        const float* buf = sm + st * (STAGE_BYTES / 4);
#pragma unroll
        for (int k = 0; k < KPT; k++) {
            const int ln = tid + k * THREADS;       // local n (stride-512 -> conflict-free LDS)
            float v = buf[ln * 3];                  // channel 0
            if (ln < nvalid && v == v) { acc_s[k] += v; acc_c[k] += 1.0f; }
        }
        __syncthreads();                            // everyone done with stage st
        if (tid == 0 && t + STAGES < TT) {
            mbar_expect_tx(mb0 + st * 8, bytes);
            bulk_g2s(sm0 + st * STAGE_BYTES, gbase + (size_t)(t + STAGES) * NN * FF,
                     bytes, mb0 + st * 8);
        }
    }

    // epilogue: write out_pred (10 tiled copies), accumulate region partials
#pragma unroll
    for (int k = 0; k < KPT; k++) {
        const int n = n0 + tid + k * THREADS;
        if (n < NN) {
            const float tm = acc_s[k] / acc_c[k];   // 0/0 -> NaN if all-NaN node
            const size_t base = (size_t)b * HH * NN + n;
#pragma unroll
            for (int h = 0; h < HH; h++) out[base + (size_t)h * NN] = tm;
            if (acc_c[k] > 0.0f) {
                const int r = g_is64 ? cid32[2 * n] : cid32[n];
                atomicAdd(&srs[r], tm);
                atomicAdd(&src[r], 1.0f);
            } else {
                const int slot = atomicAdd(&g_nan_count, 1);
                g_nan_list[slot] = b * NN + n;
            }
        }
    }
    __syncthreads();
    if (tid < RR && src[tid] > 0.0f) {
        atomicAdd(&g_rsum[b * RR + tid], srs[tid]);
        atomicAdd(&g_rcnt[b * RR + tid], src[tid]);
    }
}

// ---------------------------------------------------------------------------
// Kernel 2: one block, 640 threads = (b, r) pairs. Computes g1, regional
// means, g2, writes out_regional with NaN->g2.
// ---------------------------------------------------------------------------
__global__ void k_regional(float* __restrict__ out) {
    const int tid = threadIdx.x;          // 0..639
    const float rs = g_rsum[tid];
    const float rc = g_rcnt[tid];

    __shared__ float s_gs, s_gc, s_2s, s_2c;
    if (tid == 0) { s_gs = 0.0f; s_gc = 0.0f; s_2s = 0.0f; s_2c = 0.0f; }
    __syncthreads();

    atomicAdd(&s_gs, rs);
    atomicAdd(&s_gc, rc);
    const float reg = rs / rc;            // NaN if region empty for this b
    if (rc > 0.0f) { atomicAdd(&s_2s, reg); atomicAdd(&s_2c, 1.0f); }
    __syncthreads();

    if (tid == 0) g_g1 = s_gs / s_gc;
    const float g2 = s_2s / s_2c;
    const float val = (rc > 0.0f) ? reg : g2;

    const int b = tid / RR;
    const int r = tid % RR;
    float* o = out + (size_t)BB * HH * NN;
#pragma unroll
    for (int h = 0; h < HH; h++)
        o[(b * HH + h) * RR + r] = val;
}

// ---------------------------------------------------------------------------
// Kernel 3: patch NaN entries of out_pred with g1 (rarely any work).
// ---------------------------------------------------------------------------
__global__ void k_fix(float* __restrict__ out) {
    const int cnt = g_nan_count;
    if (cnt == 0) return;
    const float g1 = g_g1;
    const int total = cnt * HH;
    for (int i = blockIdx.x * blockDim.x + threadIdx.x; i < total;
         i += gridDim.x * blockDim.x) {
        const int idx = g_nan_list[i / HH];
        const int h = i % HH;
        const int b = idx / NN, n = idx % NN;
        out[((size_t)b * HH + h) * NN + n] = g1;
    }
}

// ---------------------------------------------------------------------------
extern "C" void kernel_launch(void* const* d_in, const int* in_sizes, int n_in,
                              void* d_out, int out_size) {
    const float* seq   = (const float*)d_in[0];
    const int*   cid32 = (const int*)d_in[1];
    float*       out   = (float*)d_out;

    cudaFuncSetAttribute(k_mean, cudaFuncAttributeMaxDynamicSharedMemorySize, SMEM_BYTES);

    k_init<<<1, 256>>>(cid32);

    dim3 grid(NBLKX, BB);
    k_mean<<<grid, THREADS, SMEM_BYTES>>>(seq, cid32, out);

    k_regional<<<1, BB * RR>>>(out);

    k_fix<<<64, 256>>>(out);
}